// round 8
// baseline (speedup 1.0000x reference)
#include <cuda_runtime.h>
#include <cstdint>
#include <math.h>

#define Bv   2
#define Lv   2048
#define DM   512
#define DI   1024
#define DS   16
#define DTR  32
#define ROWS (Bv * Lv)      // 4096
#define XPN  (DTR + 2*DS)   // 64
#define NC   32
#define CL   (Lv / NC)      // 64

// ---------------- scratch ----------------
__device__ float g_xz [2][ROWS * 2 * DI];
__device__ float g_xc [2][ROWS * DI];
__device__ float g_dbc[2][ROWS * XPN];
__device__ float g_dt [2][ROWS * DI];
__device__ float g_ys2[ROWS * 2 * DI];             // [row][dir*1024 + d], bwd rows pre-reversed
__device__ float g_sumdt[2 * Bv * NC * DI];
__device__ float g_S    [2 * Bv * NC * DS * DI];
__device__ float g_H0   [2 * Bv * NC * DS * DI];
__device__ float g_wcomb[DM * 2 * DI];             // combined weight [n=512][k=2048]
// weight scratch, layout [N,K] (tf32-rounded)
#define WT_IN(dir)    ((long)(dir) * 1048576)
#define WT_XP(dir)    (2097152 + (long)(dir) * 65536)
#define WT_DT(dir)    (2228224 + (long)(dir) * 32768)
#define WT_FUSE       (2293760)
#define WR_OUT(dir)   (2818048 + (long)(dir) * 524288)   // out_w rounded, NOT transposed
__device__ float g_wT[3866624];

__device__ __forceinline__ float silu_f(float x) { return x / (1.f + __expf(-x)); }
__device__ __forceinline__ float tf32r(float x) {
    float r; asm("cvt.rna.tf32.f32 %0, %1;" : "=f"(r) : "f"(x)); return r;
}

// warp-level tf32 MMA (family-portable PTX, sm_80+)
__device__ __forceinline__ void mma8(float d[4], const float a[4], const float b[2]) {
    asm volatile("mma.sync.aligned.m16n8k8.row.col.f32.tf32.tf32.f32 "
        "{%0,%1,%2,%3}, {%4,%5,%6,%7}, {%8,%9}, {%0,%1,%2,%3};"
        : "+f"(d[0]), "+f"(d[1]), "+f"(d[2]), "+f"(d[3])
        : "r"(__float_as_uint(a[0])), "r"(__float_as_uint(a[1])),
          "r"(__float_as_uint(a[2])), "r"(__float_as_uint(a[3])),
          "r"(__float_as_uint(b[0])), "r"(__float_as_uint(b[1])));
}
__device__ __forceinline__ void cp16(uint32_t s, const void* g) {
    asm volatile("cp.async.ca.shared.global [%0], [%1], 16;" :: "r"(s), "l"(g));
}
#define CP_COMMIT() asm volatile("cp.async.commit_group;" ::: "memory")
#define CP_WAIT0()  asm volatile("cp.async.wait_group 0;" ::: "memory")

// ---------------- weight transpose + tf32 round ----------------
__global__ void transpose_cvt(const float* __restrict__ in, float* __restrict__ outp,
                              int K, int N)
{
    __shared__ float t[32][33];
    int k0 = blockIdx.x * 32, n0 = blockIdx.y * 32;
    int x = threadIdx.x, y = threadIdx.y;
#pragma unroll
    for (int i = 0; i < 32; i += 8)
        t[y + i][x] = in[(long)(k0 + y + i) * N + n0 + x];
    __syncthreads();
#pragma unroll
    for (int i = 0; i < 32; i += 8)
        outp[(long)(n0 + y + i) * K + k0 + x] = tf32r(t[x][y + i]);
}

// ---------------- elementwise tf32 round copy (both dirs) ----------------
__global__ void round_cvt2(const float* __restrict__ a0, const float* __restrict__ a1,
                           float* __restrict__ o0, float* __restrict__ o1, int n)
{
    int i = blockIdx.x * 256 + threadIdx.x;
    int dir = i >= n;
    int j = i - dir * n;
    const float* a = dir ? a1 : a0;
    float* o = dir ? o1 : o0;
    o[j] = tf32r(a[j]);
}

// ================= tf32 mma.sync GEMM: C[M,N] = A[M,K] @ Wt[N,K]^T =================
// Tile 64 x NT, 8 warps (2 M x 4 N), occupancy 3. EPI: 0 none, 1 softplus, 2 tf32-round
template<int NT, int EPI>
__global__ __launch_bounds__(256, 3)
void gemm_mma(const float* __restrict__ A0, const float* __restrict__ A1,
              const float* __restrict__ W0, const float* __restrict__ W1,
              const float* __restrict__ b0, const float* __restrict__ b1,
              float* __restrict__ C0, float* __restrict__ C1,
              int K, int lda, int ldc, int revAmask)
{
    constexpr int WN = NT / 4;
    constexpr int NTILES = WN / 8;
    constexpr int BJ = NT / 64;          // B quads per thread
    __shared__ float As[2][64][20];
    __shared__ float Ws[2][NT][20];
    constexpr uint32_t WBUF = NT * 20 * 4;

    const int tid = threadIdx.x;
    const int wid = tid >> 5, lane = tid & 31;
    const int wm = wid & 1, wn = wid >> 1;
    const int g = lane >> 2, t = lane & 3;

    const int dir = blockIdx.z;
    const float* A = dir ? A1 : A0;
    const float* W = dir ? W1 : W0;
    const float* bias = dir ? b1 : b0;
    float* C = dir ? C1 : C0;
    const int revA = (revAmask >> dir) & 1;
    const long m0 = (long)blockIdx.y * 64;
    const int n0 = blockIdx.x * NT;

    // A loader: 1 quad per thread (64 rows x 4 quads)
    const int arow_l = tid >> 2, aq = tid & 3;
    long arow = m0 + arow_l;
    if (revA) { long bb = arow >> 11, l = arow & 2047; arow = (bb << 11) + (2047 - l); }
    const float* aptr = A + arow * lda + aq * 4;

    // B loader via cp.async
    const float* bptr[BJ]; uint32_t bsw[BJ];
#pragma unroll
    for (int j = 0; j < BJ; j++) {
        int qi = tid + j * 256;
        int row = qi >> 2, q = qi & 3;
        bptr[j] = W + (long)(n0 + row) * K + q * 4;
        bsw[j] = (uint32_t)__cvta_generic_to_shared(&Ws[0][row][q * 4]);
    }

    float acc[2][NTILES][4];
#pragma unroll
    for (int i = 0; i < 2; i++)
#pragma unroll
        for (int j = 0; j < NTILES; j++)
#pragma unroll
            for (int e = 0; e < 4; e++) acc[i][j][e] = 0.f;

    const int nb = K >> 4;
    float4 ra;

    // stage 0
#pragma unroll
    for (int j = 0; j < BJ; j++) cp16(bsw[j], bptr[j]);
    CP_COMMIT();
    ra = *(const float4*)(aptr);
    {
        float4 v = ra;
        v.x = tf32r(v.x); v.y = tf32r(v.y); v.z = tf32r(v.z); v.w = tf32r(v.w);
        *(float4*)&As[0][arow_l][aq * 4] = v;
    }
    CP_WAIT0();
    __syncthreads();

    for (int s = 0; s < nb; s++) {
        const int buf = s & 1;
        const bool more = (s + 1 < nb);
        if (more) {
            const int ko = (s + 1) * 16;
#pragma unroll
            for (int j = 0; j < BJ; j++) cp16(bsw[j] + (buf ^ 1) * WBUF, bptr[j] + ko);
            CP_COMMIT();
            ra = *(const float4*)(aptr + ko);
        }
#pragma unroll
        for (int kk = 0; kk < 2; kk++) {
            float afr[2][4];
#pragma unroll
            for (int mt = 0; mt < 2; mt++) {
                int r = wm * 32 + mt * 16;
                afr[mt][0] = As[buf][r + g     ][kk * 8 + t];
                afr[mt][1] = As[buf][r + g + 8 ][kk * 8 + t];
                afr[mt][2] = As[buf][r + g     ][kk * 8 + t + 4];
                afr[mt][3] = As[buf][r + g + 8 ][kk * 8 + t + 4];
            }
#pragma unroll
            for (int nt = 0; nt < NTILES; nt++) {
                int nc = wn * WN + nt * 8;
                float bfr[2];
                bfr[0] = Ws[buf][nc + g][kk * 8 + t];
                bfr[1] = Ws[buf][nc + g][kk * 8 + t + 4];
                mma8(acc[0][nt], afr[0], bfr);
                mma8(acc[1][nt], afr[1], bfr);
            }
        }
        if (more) {
            const int nbuf = buf ^ 1;
            float4 v = ra;
            v.x = tf32r(v.x); v.y = tf32r(v.y); v.z = tf32r(v.z); v.w = tf32r(v.w);
            *(float4*)&As[nbuf][arow_l][aq * 4] = v;
            CP_WAIT0();
            __syncthreads();
        }
    }

#pragma unroll
    for (int mt = 0; mt < 2; mt++) {
#pragma unroll
        for (int half = 0; half < 2; half++) {
            long row = m0 + wm * 32 + mt * 16 + g + half * 8;
            float* Cp = C + row * ldc + n0 + wn * WN;
#pragma unroll
            for (int nt = 0; nt < NTILES; nt++) {
                int col = nt * 8 + 2 * t;
                float2 v;
                v.x = acc[mt][nt][half * 2 + 0];
                v.y = acc[mt][nt][half * 2 + 1];
                if (bias) {
                    v.x += bias[n0 + wn * WN + col];
                    v.y += bias[n0 + wn * WN + col + 1];
                }
                if (EPI == 1) {
                    v.x = (v.x > 20.f) ? v.x : log1pf(__expf(v.x));
                    v.y = (v.y > 20.f) ? v.y : log1pf(__expf(v.y));
                }
                if (EPI == 2) { v.x = tf32r(v.x); v.y = tf32r(v.y); }
                *(float2*)(Cp + col) = v;
            }
        }
    }
}

// ---------------- depthwise causal conv + SiLU ----------------
__global__ void conv_silu_kernel(const float* __restrict__ cw0, const float* __restrict__ cb0,
                                 const float* __restrict__ cw1, const float* __restrict__ cb1)
{
    int idx = blockIdx.x * blockDim.x + threadIdx.x;
    int dir = idx >= ROWS * DI;
    int rem = idx - dir * ROWS * DI;
    const float* cw = dir ? cw1 : cw0;
    const float* cb = dir ? cb1 : cb0;
    const float* xz = g_xz[dir];
    float* xc = g_xc[dir];

    int d   = rem & (DI - 1);
    int row = rem >> 10;
    int l   = row & (Lv - 1);
    float s = cb[d];
    float w0 = cw[d * 4 + 0], w1 = cw[d * 4 + 1],
          w2 = cw[d * 4 + 2], w3 = cw[d * 4 + 3];
    const float* xp = xz + (long)row * (2 * DI) + d;
    if (l >= 3) s = fmaf(w0, xp[-3 * 2 * DI], s);
    if (l >= 2) s = fmaf(w1, xp[-2 * 2 * DI], s);
    if (l >= 1) s = fmaf(w2, xp[-1 * 2 * DI], s);
    s = fmaf(w3, xp[0], s);
    xc[rem] = silu_f(s);
}

// ================= coalesced chunked scan =================
__global__ __launch_bounds__(256)
void scan_p1(const float* __restrict__ A_log0, const float* __restrict__ A_log1)
{
    __shared__ float BC[CL][32];
    const int blk = blockIdx.x;
    const int dq  = blk & 3;
    const int c   = (blk >> 2) & (NC - 1);
    const int b   = (blk >> 7) & 1;
    const int dir = blk >> 8;
    const int d   = dq * 256 + threadIdx.x;

    const float* dbp = g_dbc[dir] + ((long)b * Lv + c * CL) * XPN;
    for (int i = threadIdx.x; i < CL * 32; i += 256)
        BC[i >> 5][i & 31] = dbp[(long)(i >> 5) * XPN + DTR + (i & 31)];
    __syncthreads();

    const float* A_log = dir ? A_log1 : A_log0;
    float An[DS];
#pragma unroll
    for (int n = 0; n < DS; n++) An[n] = -__expf(A_log[d * DS + n]);

    const float* dtp = g_dt[dir] + ((long)b * Lv + c * CL) * DI + d;
    const float* xcp = g_xc[dir] + ((long)b * Lv + c * CL) * DI + d;

    float h[DS];
#pragma unroll
    for (int n = 0; n < DS; n++) h[n] = 0.f;
    float sdt = 0.f;

    for (int l = 0; l < CL; l++) {
        float dt = dtp[l * DI];
        float xc = xcp[l * DI];
        float dx = dt * xc;
        sdt += dt;
#pragma unroll
        for (int n = 0; n < DS; n++)
            h[n] = fmaf(__expf(dt * An[n]), h[n], dx * BC[l][n]);
    }

    long sb = (((long)(dir * Bv + b) * NC + c) * DS) * DI + d;
#pragma unroll
    for (int n = 0; n < DS; n++) g_S[sb + (long)n * DI] = h[n];
    g_sumdt[((long)(dir * Bv + b) * NC + c) * DI + d] = sdt;
}

__global__ __launch_bounds__(256)
void scan_p2(const float* __restrict__ A_log0, const float* __restrict__ A_log1)
{
    int t = blockIdx.x * 256 + threadIdx.x;
    int d   = t & (DI - 1);
    int b   = (t >> 10) & 1;
    int dir = t >> 11;

    const float* A_log = dir ? A_log1 : A_log0;
    float An[DS];
#pragma unroll
    for (int n = 0; n < DS; n++) An[n] = -__expf(A_log[d * DS + n]);

    long base_sd = ((long)(dir * Bv + b) * NC) * DI + d;
    long base_S  = ((long)(dir * Bv + b) * NC) * DS * DI + d;

    float h[DS];
#pragma unroll
    for (int n = 0; n < DS; n++) h[n] = 0.f;

    for (int c = 0; c < NC; c++) {
        float sdt = g_sumdt[base_sd + (long)c * DI];
#pragma unroll
        for (int n = 0; n < DS; n++) {
            long idx = base_S + ((long)c * DS + n) * DI;
            g_H0[idx] = h[n];
            h[n] = fmaf(__expf(An[n] * sdt), h[n], g_S[idx]);
        }
    }
}

// pass 3: re-run chunks with real h0, emit y into g_ys2 (bwd rows reversed)
__global__ __launch_bounds__(256)
void scan_p3(const float* __restrict__ A_log0, const float* __restrict__ A_log1,
             const float* __restrict__ Dsk0,   const float* __restrict__ Dsk1)
{
    __shared__ float BC[CL][32];
    const int blk = blockIdx.x;
    const int dq  = blk & 3;
    const int c   = (blk >> 2) & (NC - 1);
    const int b   = (blk >> 7) & 1;
    const int dir = blk >> 8;
    const int d   = dq * 256 + threadIdx.x;

    const float* dbp = g_dbc[dir] + ((long)b * Lv + c * CL) * XPN;
    for (int i = threadIdx.x; i < CL * 32; i += 256)
        BC[i >> 5][i & 31] = dbp[(long)(i >> 5) * XPN + DTR + (i & 31)];
    __syncthreads();

    const float* A_log = dir ? A_log1 : A_log0;
    const float* Dsk   = dir ? Dsk1 : Dsk0;
    float An[DS];
#pragma unroll
    for (int n = 0; n < DS; n++) An[n] = -__expf(A_log[d * DS + n]);
    float Dd = Dsk[d];

    const float* dtp = g_dt[dir] + ((long)b * Lv + c * CL) * DI + d;
    const float* xcp = g_xc[dir] + ((long)b * Lv + c * CL) * DI + d;
    const float* zp  = g_xz[dir] + ((long)b * Lv + c * CL) * (2 * DI) + DI + d;

    long hb = (((long)(dir * Bv + b) * NC + c) * DS) * DI + d;
    float h[DS];
#pragma unroll
    for (int n = 0; n < DS; n++) h[n] = g_H0[hb + (long)n * DI];

    for (int l = 0; l < CL; l++) {
        float dt = dtp[l * DI];
        float xc = xcp[l * DI];
        float zv = zp[l * 2 * DI];
        float dx = dt * xc;
        float y = xc * Dd;
#pragma unroll
        for (int n = 0; n < DS; n++) {
            h[n] = fmaf(__expf(dt * An[n]), h[n], dx * BC[l][n]);
            y = fmaf(h[n], BC[l][DS + n], y);
        }
        int lrow = c * CL + l;
        if (dir) lrow = Lv - 1 - lrow;            // bwd: store reversed
        g_ys2[((long)b * Lv + lrow) * (2 * DI) + dir * DI + d] = y * silu_f(zv);
    }
}

// ---------------- launch ----------------
extern "C" void kernel_launch(void* const* d_in, const int* in_sizes, int n_in,
                              void* d_out, int out_size)
{
    const float* hidden = (const float*)d_in[0];
    float* out = (float*)d_out;

    float *xz, *xc, *dbc, *dtb, *ys2, *wT, *wcomb;
    cudaGetSymbolAddress((void**)&xz,    g_xz);
    cudaGetSymbolAddress((void**)&xc,    g_xc);
    cudaGetSymbolAddress((void**)&dbc,   g_dbc);
    cudaGetSymbolAddress((void**)&dtb,   g_dt);
    cudaGetSymbolAddress((void**)&ys2,   g_ys2);
    cudaGetSymbolAddress((void**)&wT,    g_wT);
    cudaGetSymbolAddress((void**)&wcomb, g_wcomb);

    const float* p[2][9];
    for (int dir = 0; dir < 2; dir++)
        for (int k = 0; k < 9; k++)
            p[dir][k] = (const float*)d_in[1 + 9 * dir + k];
    const float* fuse_w = (const float*)d_in[19];
    const float* fuse_b = (const float*)d_in[20];

    const long SXZ = (long)ROWS * 2 * DI, SXC = (long)ROWS * DI;
    const long SDB = (long)ROWS * XPN;

    const dim3 tb(32, 8);
    for (int dir = 0; dir < 2; dir++) {
        transpose_cvt<<<dim3(512 / 32, 2048 / 32), tb>>>(p[dir][0], wT + WT_IN(dir),  512, 2048);
        transpose_cvt<<<dim3(1024 / 32, 64 / 32),  tb>>>(p[dir][3], wT + WT_XP(dir),  1024, 64);
        transpose_cvt<<<dim3(32 / 32, 1024 / 32),  tb>>>(p[dir][4], wT + WT_DT(dir),  32, 1024);
    }
    transpose_cvt<<<dim3(1024 / 32, 512 / 32), tb>>>(fuse_w, wT + WT_FUSE, 1024, 512);
    round_cvt2<<<(2 * 1024 * 512) / 256, 256>>>(p[0][8], p[1][8],
                                                wT + WR_OUT(0), wT + WR_OUT(1), 1024 * 512);

    // Precompute combined weight: wcomb[n][dir*1024+kk] = sum_j fuse^T[n][dir*512+j] * out_w[kk][j]
    gemm_mma<128, 2><<<dim3(8, 8, 2), 256>>>(
        wT + WT_FUSE, wT + WT_FUSE + DM, wT + WR_OUT(0), wT + WR_OUT(1),
        nullptr, nullptr, wcomb, wcomb + DI, DM, 2 * DM, 2 * DI, 0);

    // 1. in_proj (bwd reads rows reversed)
    gemm_mma<128, 0><<<dim3(16, 64, 2), 256>>>(
        hidden, hidden, wT + WT_IN(0), wT + WT_IN(1), nullptr, nullptr,
        xz, xz + SXZ, DM, DM, 2 * DI, 0b10);

    // 2. conv + silu
    conv_silu_kernel<<<(2 * ROWS * DI) / 256, 256>>>(p[0][1], p[0][2], p[1][1], p[1][2]);

    // 3. xproj
    gemm_mma<64, 0><<<dim3(1, 64, 2), 256>>>(
        xc, xc + SXC, wT + WT_XP(0), wT + WT_XP(1), nullptr, nullptr,
        dbc, dbc + SDB, DI, DI, XPN, 0);

    // 4. dt proj + softplus
    gemm_mma<128, 1><<<dim3(8, 64, 2), 256>>>(
        dbc, dbc + SDB, wT + WT_DT(0), wT + WT_DT(1), p[0][5], p[1][5],
        dtb, dtb + SXC, DTR, XPN, DI, 0);

    // 5. coalesced chunked scan -> g_ys2 (bwd reversed)
    scan_p1<<<2 * Bv * NC * (DI / 256), 256>>>(p[0][6], p[1][6]);
    scan_p2<<<(2 * Bv * DI) / 256, 256>>>(p[0][6], p[1][6]);
    scan_p3<<<2 * Bv * NC * (DI / 256), 256>>>(p[0][6], p[1][6], p[0][7], p[1][7]);

    // 6. single combined output GEMM: (4096,2048)@wcomb^T + fuse_b -> out
    gemm_mma<64, 0><<<dim3(8, 64, 1), 256>>>(
        ys2, ys2, wcomb, wcomb, fuse_b, fuse_b,
        out, out, 2 * DI, 2 * DI, DM, 0);
}